// round 2
// baseline (speedup 1.0000x reference)
#include <cuda_runtime.h>
#include <cstdint>
#include <math.h>

#define B_   32
#define S_   128
#define H_   512
#define D_   512
#define V_   32000
#define F_   768
#define G4   2048
#define NSTEP 129
#define MROWS 4096

__device__ float g_Xg  [NSTEP * B_ * D_];
__device__ float g_pre0[NSTEP * B_ * G4];
__device__ float g_M1  [D_ * G4];
__device__ float g_b0  [G4];
__device__ float g_b1p [G4];
__device__ float g_h0s [2][B_ * H_];
__device__ float g_c0s [B_ * H_];
__device__ float g_h1s [2][B_ * H_];
__device__ float g_c1s [B_ * H_];
__device__ float g_Hs  [MROWS * H_];
__device__ float g_Ys  [MROWS * D_];

__device__ __forceinline__ float f2tf32(float x) {
    float y; asm("cvt.rna.tf32.f32 %0, %1;" : "=f"(y) : "f"(x)); return y;
}
__device__ __forceinline__ float sigf(float x) { return 1.f / (1.f + expf(-x)); }

// ---------------- prep kernels ----------------
__global__ void init_state_k(const float* __restrict__ h0, const float* __restrict__ c0) {
    int i = blockIdx.x * blockDim.x + threadIdx.x;
    if (i < B_ * H_) {
        g_h0s[0][i] = h0[i];           g_h1s[0][i] = h0[B_ * H_ + i];
        g_c0s[i]    = c0[i];           g_c1s[i]    = c0[B_ * H_ + i];
    }
}
__global__ void bias_prep_k(const float* __restrict__ bw, const float* __restrict__ bu) {
    int j = blockIdx.x * blockDim.x + threadIdx.x;
    if (j < G4) { g_b0[j] = bw[j] + bu[j]; g_b1p[j] = bw[G4 + j] + bu[G4 + j]; }
}
__global__ void b1_fold_k(const float* __restrict__ bxh0, const float* __restrict__ Uh1) {
    int j = blockIdx.x * blockDim.x + threadIdx.x;
    if (j < G4) {
        float s = g_b1p[j];
        #pragma unroll 4
        for (int d = 0; d < D_; d++) s += bxh0[d] * Uh1[(size_t)d * G4 + j];
        g_b1p[j] = s;
    }
}
__global__ void im_proj_k(const float* __restrict__ im, const float* __restrict__ Wim,
                          const float* __restrict__ bim) {
    int idx = blockIdx.x * blockDim.x + threadIdx.x;
    if (idx < B_ * D_) {
        int b = idx >> 9, d = idx & 511;
        float s = bim[d];
        #pragma unroll 4
        for (int f = 0; f < F_; f++) s += im[b * F_ + f] * Wim[(size_t)f * D_ + d];
        g_Xg[idx] = s;
    }
}
__global__ void gather_k(const int* __restrict__ tok, const float* __restrict__ embed) {
    int i = blockIdx.x * blockDim.x + threadIdx.x;
    if (i < S_ * B_ * (D_ / 4)) {
        int d4 = i & 127, r = i >> 7, b = r & 31, s = r >> 5;
        float4 v = ((const float4*)(embed + (size_t)tok[b * S_ + s] * D_))[d4];
        ((float4*)(g_Xg + ((size_t)(1 + s) * B_ + b) * D_))[d4] = v;
    }
}

// ---------------- TF32 GEMM: C[MxN] = A[MxK] @ B[KxN] (+bias) ----------------
// BM=BN=128, BK=32, 256 thr, warps 4(M)x2(N), warp tile 32x64, mma m16n8k8, dbl-buffered
__global__ void __launch_bounds__(256) gemm_tf32(
    const float* __restrict__ A, const float* __restrict__ B,
    float* __restrict__ C, const float* __restrict__ bias, int M, int N, int K)
{
    extern __shared__ float sh[];
    float* As = sh;                  // 2 x [128][33]
    float* Bs = sh + 2 * 128 * 33;   // 2 x [32][132]
    const int tid = threadIdx.x, lane = tid & 31, warp = tid >> 5;
    const int gid = lane >> 2, tig = lane & 3;
    const int wm = warp & 3, wn = warp >> 2;
    const int m0 = blockIdx.x * 128, n0 = blockIdx.y * 128;

    float acc[2][8][4];
    #pragma unroll
    for (int i = 0; i < 2; i++)
        #pragma unroll
        for (int j = 0; j < 8; j++) { acc[i][j][0]=0.f; acc[i][j][1]=0.f; acc[i][j][2]=0.f; acc[i][j][3]=0.f; }

    const int ar = tid >> 3, ak = (tid & 7) << 2;
    const int bk = tid >> 5, bn = (tid & 31) << 2;
    const int KT = K >> 5;
    float4 av[4], bv[4];

    auto ldg_tile = [&](int kt) {
        #pragma unroll
        for (int p = 0; p < 4; p++) {
            int row = m0 + ar + p * 32;
            av[p] = (row < M) ? *(const float4*)(A + (size_t)row * K + kt * 32 + ak)
                              : make_float4(0.f, 0.f, 0.f, 0.f);
            bv[p] = *(const float4*)(B + (size_t)(kt * 32 + bk + p * 8) * N + n0 + bn);
        }
    };
    auto sts_tile = [&](int buf) {
        float* Ad = As + buf * (128 * 33);
        float* Bd = Bs + buf * (32 * 132);
        #pragma unroll
        for (int p = 0; p < 4; p++) {
            float* a = Ad + (ar + p * 32) * 33 + ak;
            a[0]=f2tf32(av[p].x); a[1]=f2tf32(av[p].y); a[2]=f2tf32(av[p].z); a[3]=f2tf32(av[p].w);
            float* b = Bd + (bk + p * 8) * 132 + bn;
            b[0]=f2tf32(bv[p].x); b[1]=f2tf32(bv[p].y); b[2]=f2tf32(bv[p].z); b[3]=f2tf32(bv[p].w);
        }
    };

    ldg_tile(0); sts_tile(0); __syncthreads();

    for (int kt = 0; kt < KT; kt++) {
        const int nxt = kt + 1;
        if (nxt < KT) ldg_tile(nxt);
        const float* Ab = As + (kt & 1) * (128 * 33);
        const float* Bb = Bs + (kt & 1) * (32 * 132);
        #pragma unroll
        for (int kk = 0; kk < 32; kk += 8) {
            uint32_t af[2][4], bf[8][2];
            #pragma unroll
            for (int mi = 0; mi < 2; mi++) {
                int r = wm * 32 + mi * 16 + gid;
                af[mi][0] = __float_as_uint(Ab[r       * 33 + kk + tig]);
                af[mi][1] = __float_as_uint(Ab[(r + 8) * 33 + kk + tig]);
                af[mi][2] = __float_as_uint(Ab[r       * 33 + kk + tig + 4]);
                af[mi][3] = __float_as_uint(Ab[(r + 8) * 33 + kk + tig + 4]);
            }
            #pragma unroll
            for (int ni = 0; ni < 8; ni++) {
                int cx = wn * 64 + ni * 8 + gid;
                bf[ni][0] = __float_as_uint(Bb[(kk + tig)     * 132 + cx]);
                bf[ni][1] = __float_as_uint(Bb[(kk + tig + 4) * 132 + cx]);
            }
            #pragma unroll
            for (int mi = 0; mi < 2; mi++)
                #pragma unroll
                for (int ni = 0; ni < 8; ni++)
                    asm volatile(
                        "mma.sync.aligned.m16n8k8.row.col.f32.tf32.tf32.f32 "
                        "{%0,%1,%2,%3}, {%4,%5,%6,%7}, {%8,%9}, {%0,%1,%2,%3};"
                        : "+f"(acc[mi][ni][0]), "+f"(acc[mi][ni][1]),
                          "+f"(acc[mi][ni][2]), "+f"(acc[mi][ni][3])
                        : "r"(af[mi][0]), "r"(af[mi][1]), "r"(af[mi][2]), "r"(af[mi][3]),
                          "r"(bf[ni][0]), "r"(bf[ni][1]));
        }
        if (nxt < KT) { sts_tile(nxt & 1); __syncthreads(); }
    }

    #pragma unroll
    for (int mi = 0; mi < 2; mi++) {
        int r = m0 + wm * 32 + mi * 16 + gid;
        #pragma unroll
        for (int ni = 0; ni < 8; ni++) {
            int cx = n0 + wn * 64 + ni * 8 + tig * 2;
            float b0v = bias ? bias[cx] : 0.f, b1v = bias ? bias[cx + 1] : 0.f;
            if (r < M) {
                C[(size_t)r * N + cx]     = acc[mi][ni][0] + b0v;
                C[(size_t)r * N + cx + 1] = acc[mi][ni][1] + b1v;
            }
            if (r + 8 < M) {
                C[(size_t)(r + 8) * N + cx]     = acc[mi][ni][2] + b0v;
                C[(size_t)(r + 8) * N + cx + 1] = acc[mi][ni][3] + b1v;
            }
        }
    }
}

// ---------------- LSTM step kernels (fp32, 128 CTAs x 256 thr) ----------------
// CTA = 4 hidden units (u0..u0+3). warp w: gate g=w&3, k-half=w>>5bit. lane=batch.
__global__ void __launch_bounds__(256) lstm_l0(int t, int p, const float* __restrict__ W) {
    extern __shared__ float sh[];
    float* hT = sh;                  // [512][33]
    float* pb = sh + 512 * 33;       // [8][4][32]
    const int tid = threadIdx.x;
    const float* hp = g_h0s[p];
    for (int i = tid; i < B_ * H_; i += 256) { int b = i >> 9, k = i & 511; hT[k * 33 + b] = hp[i]; }
    __syncthreads();

    const int lane = tid & 31, w = tid >> 5, g = w & 3, half = w >> 2;
    const int u0 = blockIdx.x << 2;
    const float* Wp = W + (size_t)(half * 256) * G4 + g * 512 + u0;
    const float* xp = hT + (half * 256) * 33 + lane;
    float a0 = 0.f, a1 = 0.f, a2 = 0.f, a3 = 0.f;
    #pragma unroll 8
    for (int kk = 0; kk < 256; kk++) {
        float x = xp[kk * 33];
        float4 wv = *(const float4*)(Wp + (size_t)kk * G4);
        a0 = fmaf(wv.x, x, a0); a1 = fmaf(wv.y, x, a1);
        a2 = fmaf(wv.z, x, a2); a3 = fmaf(wv.w, x, a3);
    }
    float* q = pb + w * 128 + lane;
    q[0] = a0; q[32] = a1; q[64] = a2; q[96] = a3;
    __syncthreads();

    if (tid < 128) {
        int u = tid >> 5, b = tid & 31, uu = u0 + u;
        const float* pre = g_pre0 + ((size_t)t * B_ + b) * G4;
        float fg = pb[0*128 + u*32 + b] + pb[4*128 + u*32 + b] + pre[uu];
        float ig = pb[1*128 + u*32 + b] + pb[5*128 + u*32 + b] + pre[512 + uu];
        float og = pb[2*128 + u*32 + b] + pb[6*128 + u*32 + b] + pre[1024 + uu];
        float cc = pb[3*128 + u*32 + b] + pb[7*128 + u*32 + b] + pre[1536 + uu];
        fg = sigf(fg); ig = sigf(ig); og = sigf(og); cc = tanhf(cc);
        int idx = b * H_ + uu;
        float cn = fg * g_c0s[idx] + ig * cc;
        g_c0s[idx] = cn;
        g_h0s[p ^ 1][idx] = og * tanhf(cn);
    }
}

__global__ void __launch_bounds__(256) lstm_l1(int t, int p, const float* __restrict__ W1) {
    extern __shared__ float sh[];
    float* hT = sh;
    float* pb = sh + 512 * 33;
    const int tid = threadIdx.x;
    const int lane = tid & 31, w = tid >> 5, g = w & 3, half = w >> 2;
    const int u0 = blockIdx.x << 2;
    const float* xp = hT + (half * 256) * 33 + lane;
    float a0 = 0.f, a1 = 0.f, a2 = 0.f, a3 = 0.f;

    const float* h1p = g_h1s[p];
    for (int i = tid; i < B_ * H_; i += 256) { int b = i >> 9, k = i & 511; hT[k * 33 + b] = h1p[i]; }
    __syncthreads();
    {
        const float* Wp = W1 + (size_t)(half * 256) * G4 + g * 512 + u0;
        #pragma unroll 8
        for (int kk = 0; kk < 256; kk++) {
            float x = xp[kk * 33];
            float4 wv = *(const float4*)(Wp + (size_t)kk * G4);
            a0 = fmaf(wv.x, x, a0); a1 = fmaf(wv.y, x, a1);
            a2 = fmaf(wv.z, x, a2); a3 = fmaf(wv.w, x, a3);
        }
    }
    __syncthreads();
    const float* h0n = g_h0s[p ^ 1];
    for (int i = tid; i < B_ * H_; i += 256) { int b = i >> 9, k = i & 511; hT[k * 33 + b] = h0n[i]; }
    __syncthreads();
    {
        const float* Wp = g_M1 + (size_t)(half * 256) * G4 + g * 512 + u0;
        #pragma unroll 8
        for (int kk = 0; kk < 256; kk++) {
            float x = xp[kk * 33];
            float4 wv = *(const float4*)(Wp + (size_t)kk * G4);
            a0 = fmaf(wv.x, x, a0); a1 = fmaf(wv.y, x, a1);
            a2 = fmaf(wv.z, x, a2); a3 = fmaf(wv.w, x, a3);
        }
    }
    float* q = pb + w * 128 + lane;
    q[0] = a0; q[32] = a1; q[64] = a2; q[96] = a3;
    __syncthreads();

    if (tid < 128) {
        int u = tid >> 5, b = tid & 31, uu = u0 + u;
        float fg = pb[0*128 + u*32 + b] + pb[4*128 + u*32 + b] + g_b1p[uu];
        float ig = pb[1*128 + u*32 + b] + pb[5*128 + u*32 + b] + g_b1p[512 + uu];
        float og = pb[2*128 + u*32 + b] + pb[6*128 + u*32 + b] + g_b1p[1024 + uu];
        float cc = pb[3*128 + u*32 + b] + pb[7*128 + u*32 + b] + g_b1p[1536 + uu];
        fg = sigf(fg); ig = sigf(ig); og = sigf(og); cc = tanhf(cc);
        int idx = b * H_ + uu;
        float cn = fg * g_c1s[idx] + ig * cc;
        g_c1s[idx] = cn;
        float hn = og * tanhf(cn);
        g_h1s[p ^ 1][idx] = hn;
        if (t > 0) g_Hs[((size_t)b * S_ + (t - 1)) * H_ + uu] = hn;
    }
}

// ---------------- launch ----------------
extern "C" void kernel_launch(void* const* d_in, const int* in_sizes, int n_in,
                              void* d_out, int out_size) {
    const float* im    = (const float*)d_in[0];
    const int*   tok   = (const int*)  d_in[1];
    const float* h0    = (const float*)d_in[2];
    const float* c0    = (const float*)d_in[3];
    const float* embed = (const float*)d_in[4];
    const float* Wim   = (const float*)d_in[5];
    const float* bim   = (const float*)d_in[6];
    const float* Wh    = (const float*)d_in[7];
    const float* bw    = (const float*)d_in[8];
    const float* Uh    = (const float*)d_in[9];
    const float* bu    = (const float*)d_in[10];
    const float* Wxh   = (const float*)d_in[11];
    const float* bxh   = (const float*)d_in[12];
    const float* Wc    = (const float*)d_in[13];
    const float* bc    = (const float*)d_in[14];
    float* out = (float*)d_out;

    const size_t GEMM_SM = 2 * (128 * 33 + 32 * 132) * sizeof(float);   // 67584
    const size_t STEP_SM = (512 * 33 + 8 * 128) * sizeof(float);        // 71680
    cudaFuncSetAttribute(gemm_tf32, cudaFuncAttributeMaxDynamicSharedMemorySize, (int)GEMM_SM);
    cudaFuncSetAttribute(lstm_l0,   cudaFuncAttributeMaxDynamicSharedMemorySize, (int)STEP_SM);
    cudaFuncSetAttribute(lstm_l1,   cudaFuncAttributeMaxDynamicSharedMemorySize, (int)STEP_SM);

    void *pXg, *pPre0, *pM1, *pB0, *pHs, *pYs;
    cudaGetSymbolAddress(&pXg,  g_Xg);
    cudaGetSymbolAddress(&pPre0,g_pre0);
    cudaGetSymbolAddress(&pM1,  g_M1);
    cudaGetSymbolAddress(&pB0,  g_b0);
    cudaGetSymbolAddress(&pHs,  g_Hs);
    cudaGetSymbolAddress(&pYs,  g_Ys);

    init_state_k<<<(B_ * H_ + 255) / 256, 256>>>(h0, c0);
    bias_prep_k<<<G4 / 256, 256>>>(bw, bu);
    b1_fold_k<<<G4 / 256, 256>>>(bxh, Uh + (size_t)D_ * G4);
    im_proj_k<<<(B_ * D_ + 255) / 256, 256>>>(im, Wim, bim);
    gather_k<<<(S_ * B_ * (D_ / 4) + 255) / 256, 256>>>(tok, embed);

    // pre0 = Xg @ Uh0 + (bw0+bu0)   [4128 x 2048]
    gemm_tf32<<<dim3(33, 16), 256, GEMM_SM>>>((const float*)pXg, Uh, (float*)pPre0,
                                              (const float*)pB0, NSTEP * B_, G4, D_);
    // M1 = Wxh0 @ Uh1               [512 x 2048]
    gemm_tf32<<<dim3(4, 16), 256, GEMM_SM>>>(Wxh, Uh + (size_t)D_ * G4, (float*)pM1,
                                             nullptr, H_, G4, H_);

    const float* Wh0 = Wh;
    const float* Wh1 = Wh + (size_t)H_ * G4;
    int p = 0;
    for (int t = 0; t < NSTEP; t++) {
        lstm_l0<<<128, 256, STEP_SM>>>(t, p, Wh0);
        lstm_l1<<<128, 256, STEP_SM>>>(t, p, Wh1);
        p ^= 1;
    }

    // Ys = Hs @ Wxh1 + bxh1         [4096 x 512]
    gemm_tf32<<<dim3(32, 4), 256, GEMM_SM>>>((const float*)pHs, Wxh + (size_t)H_ * D_,
                                             (float*)pYs, bxh + D_, MROWS, D_, H_);
    // logits = Ys @ Wc + bc         [4096 x 32000]
    gemm_tf32<<<dim3(32, 250), 256, GEMM_SM>>>((const float*)pYs, Wc, out, bc,
                                               MROWS, V_, D_);
}

// round 3
// speedup vs baseline: 2.2760x; 2.2760x over previous
#include <cuda_runtime.h>
#include <cstdint>
#include <math.h>

#define B_   32
#define S_   128
#define H_   512
#define D_   512
#define V_   32000
#define F_   768
#define G4   2048
#define NSTEP 129
#define MROWS 4096

__device__ float g_Xg  [NSTEP * B_ * D_];
__device__ float g_pre0[NSTEP * B_ * G4];
__device__ float g_M1  [D_ * G4];
__device__ float g_b0  [G4];
__device__ float g_b1p [G4];
__device__ float g_h0s [2][B_ * H_];
__device__ float g_c0s [B_ * H_];
__device__ float g_h1s [2][B_ * H_];
__device__ float g_c1s [B_ * H_];
__device__ float g_Hs  [MROWS * H_];
__device__ float g_Ys  [MROWS * D_];
__device__ volatile unsigned g_phase_v;
__device__ unsigned g_count;

__device__ __forceinline__ float f2tf32(float x) {
    float y; asm("cvt.rna.tf32.f32 %0, %1;" : "=f"(y) : "f"(x)); return y;
}
__device__ __forceinline__ float sigf(float x) { return 1.f / (1.f + expf(-x)); }

// ---------------- prep kernels ----------------
__global__ void init_state_k(const float* __restrict__ h0, const float* __restrict__ c0) {
    int i = blockIdx.x * blockDim.x + threadIdx.x;
    if (i < B_ * H_) {
        g_h0s[0][i] = h0[i];           g_h1s[0][i] = h0[B_ * H_ + i];
        g_c0s[i]    = c0[i];           g_c1s[i]    = c0[B_ * H_ + i];
    }
}
__global__ void bias_prep_k(const float* __restrict__ bw, const float* __restrict__ bu) {
    int j = blockIdx.x * blockDim.x + threadIdx.x;
    if (j < G4) { g_b0[j] = bw[j] + bu[j]; g_b1p[j] = bw[G4 + j] + bu[G4 + j]; }
}
// g_b1p[j] += sum_d bxh0[d]*Uh1[d][j]; 64 blocks x 256 thr; 8 threads reduce one j
__global__ void b1_fold_k(const float* __restrict__ bxh0, const float* __restrict__ Uh1) {
    __shared__ float red[256];
    int j  = blockIdx.x * 32 + (threadIdx.x & 31);
    int sl = threadIdx.x >> 5;
    float s = 0.f;
    #pragma unroll 8
    for (int d = sl * 64; d < sl * 64 + 64; d++) s += bxh0[d] * Uh1[(size_t)d * G4 + j];
    red[threadIdx.x] = s;
    __syncthreads();
    if (threadIdx.x < 32) {
        float t = red[threadIdx.x];
        #pragma unroll
        for (int k = 1; k < 8; k++) t += red[k * 32 + threadIdx.x];
        g_b1p[j] += t;
    }
}
__global__ void gather_k(const int* __restrict__ tok, const float* __restrict__ embed) {
    int i = blockIdx.x * blockDim.x + threadIdx.x;
    if (i < S_ * B_ * (D_ / 4)) {
        int d4 = i & 127, r = i >> 7, b = r & 31, s = r >> 5;
        float4 v = ((const float4*)(embed + (size_t)tok[b * S_ + s] * D_))[d4];
        ((float4*)(g_Xg + ((size_t)(1 + s) * B_ + b) * D_))[d4] = v;
    }
}

// ---------------- TF32 GEMM: C[MxN] = A[MxK] @ B[KxN] (+bias) ----------------
// BM=BN=128, BK=32, 256 thr, warp tile 32x64, mma m16n8k8, dbl buffer.
// Pads: A stride 36, B stride 136 -> conflict-free fragment LDS.
#define ASTR 36
#define BSTR 136
__global__ void __launch_bounds__(256) gemm_tf32(
    const float* __restrict__ A, const float* __restrict__ B,
    float* __restrict__ C, const float* __restrict__ bias, int M, int N, int K)
{
    extern __shared__ float sh[];
    float* As = sh;                      // 2 x [128][36]
    float* Bs = sh + 2 * 128 * ASTR;     // 2 x [32][136]
    const int tid = threadIdx.x, lane = tid & 31, warp = tid >> 5;
    const int gid = lane >> 2, tig = lane & 3;
    const int wm = warp & 3, wn = warp >> 2;
    const int m0 = blockIdx.x * 128, n0 = blockIdx.y * 128;

    float acc[2][8][4];
    #pragma unroll
    for (int i = 0; i < 2; i++)
        #pragma unroll
        for (int j = 0; j < 8; j++) { acc[i][j][0]=0.f; acc[i][j][1]=0.f; acc[i][j][2]=0.f; acc[i][j][3]=0.f; }

    const int ar = tid >> 3, ak = (tid & 7) << 2;
    const int bk = tid >> 5, bn = (tid & 31) << 2;
    const int KT = K >> 5;
    float4 av[4], bv[4];

    auto ldg_tile = [&](int kt) {
        #pragma unroll
        for (int p = 0; p < 4; p++) {
            int row = m0 + ar + p * 32;
            av[p] = (row < M) ? *(const float4*)(A + (size_t)row * K + kt * 32 + ak)
                              : make_float4(0.f, 0.f, 0.f, 0.f);
            bv[p] = *(const float4*)(B + (size_t)(kt * 32 + bk + p * 8) * N + n0 + bn);
        }
    };
    auto sts_tile = [&](int buf) {
        float* Ad = As + buf * (128 * ASTR);
        float* Bd = Bs + buf * (32 * BSTR);
        #pragma unroll
        for (int p = 0; p < 4; p++) {
            float* a = Ad + (ar + p * 32) * ASTR + ak;
            a[0]=f2tf32(av[p].x); a[1]=f2tf32(av[p].y); a[2]=f2tf32(av[p].z); a[3]=f2tf32(av[p].w);
            float* b = Bd + (bk + p * 8) * BSTR + bn;
            b[0]=f2tf32(bv[p].x); b[1]=f2tf32(bv[p].y); b[2]=f2tf32(bv[p].z); b[3]=f2tf32(bv[p].w);
        }
    };

    ldg_tile(0); sts_tile(0); __syncthreads();

    for (int kt = 0; kt < KT; kt++) {
        const int nxt = kt + 1;
        if (nxt < KT) ldg_tile(nxt);
        const float* Ab = As + (kt & 1) * (128 * ASTR);
        const float* Bb = Bs + (kt & 1) * (32 * BSTR);
        #pragma unroll
        for (int kk = 0; kk < 32; kk += 8) {
            uint32_t af[2][4], bf[8][2];
            #pragma unroll
            for (int mi = 0; mi < 2; mi++) {
                int r = wm * 32 + mi * 16 + gid;
                af[mi][0] = __float_as_uint(Ab[r       * ASTR + kk + tig]);
                af[mi][1] = __float_as_uint(Ab[(r + 8) * ASTR + kk + tig]);
                af[mi][2] = __float_as_uint(Ab[r       * ASTR + kk + tig + 4]);
                af[mi][3] = __float_as_uint(Ab[(r + 8) * ASTR + kk + tig + 4]);
            }
            #pragma unroll
            for (int ni = 0; ni < 8; ni++) {
                int cx = wn * 64 + ni * 8 + gid;
                bf[ni][0] = __float_as_uint(Bb[(kk + tig)     * BSTR + cx]);
                bf[ni][1] = __float_as_uint(Bb[(kk + tig + 4) * BSTR + cx]);
            }
            #pragma unroll
            for (int mi = 0; mi < 2; mi++)
                #pragma unroll
                for (int ni = 0; ni < 8; ni++)
                    asm volatile(
                        "mma.sync.aligned.m16n8k8.row.col.f32.tf32.tf32.f32 "
                        "{%0,%1,%2,%3}, {%4,%5,%6,%7}, {%8,%9}, {%0,%1,%2,%3};"
                        : "+f"(acc[mi][ni][0]), "+f"(acc[mi][ni][1]),
                          "+f"(acc[mi][ni][2]), "+f"(acc[mi][ni][3])
                        : "r"(af[mi][0]), "r"(af[mi][1]), "r"(af[mi][2]), "r"(af[mi][3]),
                          "r"(bf[ni][0]), "r"(bf[ni][1]));
        }
        if (nxt < KT) { sts_tile(nxt & 1); __syncthreads(); }
    }

    #pragma unroll
    for (int mi = 0; mi < 2; mi++) {
        int r = m0 + wm * 32 + mi * 16 + gid;
        #pragma unroll
        for (int ni = 0; ni < 8; ni++) {
            int cx = n0 + wn * 64 + ni * 8 + tig * 2;
            float b0v = bias ? bias[cx] : 0.f, b1v = bias ? bias[cx + 1] : 0.f;
            if (r < M) {
                C[(size_t)r * N + cx]     = acc[mi][ni][0] + b0v;
                C[(size_t)r * N + cx + 1] = acc[mi][ni][1] + b1v;
            }
            if (r + 8 < M) {
                C[(size_t)(r + 8) * N + cx]     = acc[mi][ni][2] + b0v;
                C[(size_t)(r + 8) * N + cx + 1] = acc[mi][ni][3] + b1v;
            }
        }
    }
}

// ---------------- persistent LSTM recurrence ----------------
// 128 CTAs x 256 thr, all co-resident. CTA owns 4 hidden units for both layers.
// Weights (Wh0, Wh1, M1 slices: 3 x 32KB) live in smem for the whole kernel.
__device__ __forceinline__ void grid_sync_() {
    __syncthreads();
    if (threadIdx.x == 0) {
        __threadfence();
        unsigned ph = g_phase_v;
        if (atomicAdd(&g_count, 1u) == gridDim.x - 1u) {
            g_count = 0u;
            __threadfence();
            g_phase_v = ph + 1u;
        } else {
            while (g_phase_v == ph) { }
        }
        __threadfence();
    }
    __syncthreads();
}

#define SM_W0 0
#define SM_W1 8192
#define SM_M1 16384
#define SM_HT 24576
#define SM_PB (24576 + 16896)
#define PERS_SMEM ((SM_PB + 1024) * 4)   // 169,984 B

__global__ void __launch_bounds__(256, 1) lstm_pers(const float* __restrict__ Wh0,
                                                    const float* __restrict__ Wh1) {
    extern __shared__ float sh[];
    float4* Ws0 = (float4*)(sh + SM_W0);
    float4* Ws1 = (float4*)(sh + SM_W1);
    float4* Ms1 = (float4*)(sh + SM_M1);
    float*  hT  = sh + SM_HT;     // [512][33]
    float*  pb  = sh + SM_PB;     // [8][4][32]
    const int tid = threadIdx.x, lane = tid & 31, w = tid >> 5;
    const int half = w >> 2;
    const int u0 = blockIdx.x << 2;

    for (int f4 = tid; f4 < 2048; f4 += 256) {
        int ww = f4 >> 8, kk = f4 & 255;
        int gg = ww & 3, hh = ww >> 2;
        size_t off = (size_t)(hh * 256 + kk) * G4 + gg * 512 + u0;
        Ws0[f4] = *(const float4*)(Wh0  + off);
        Ws1[f4] = *(const float4*)(Wh1  + off);
        Ms1[f4] = *(const float4*)(g_M1 + off);
    }

    const float4* W0p = Ws0 + (w << 8);
    const float4* W1p = Ws1 + (w << 8);
    const float4* M1p = Ms1 + (w << 8);
    const float*  xp  = hT + (half * 256) * 33 + lane;

    int p = 0;
    for (int t = 0; t < NSTEP; t++) {
        __syncthreads();
        // ---- layer1 part A: h1[p] @ Wh1 (independent of layer0) ----
        {
            const float* hp = g_h1s[p];
            #pragma unroll 8
            for (int i = tid; i < B_ * H_; i += 256) { int b = i >> 9, k = i & 511; hT[k * 33 + b] = hp[i]; }
        }
        __syncthreads();
        float s0=0.f,s1=0.f,s2=0.f,s3=0.f;
        #pragma unroll 8
        for (int kk = 0; kk < 256; kk++) {
            float x = xp[kk * 33]; float4 wv = W1p[kk];
            s0=fmaf(wv.x,x,s0); s1=fmaf(wv.y,x,s1); s2=fmaf(wv.z,x,s2); s3=fmaf(wv.w,x,s3);
        }
        __syncthreads();
        // ---- layer0: h0[p] @ Wh0 + pre0[t] ----
        {
            const float* hp = g_h0s[p];
            #pragma unroll 8
            for (int i = tid; i < B_ * H_; i += 256) { int b = i >> 9, k = i & 511; hT[k * 33 + b] = hp[i]; }
        }
        __syncthreads();
        float a0=0.f,a1=0.f,a2=0.f,a3=0.f;
        #pragma unroll 8
        for (int kk = 0; kk < 256; kk++) {
            float x = xp[kk * 33]; float4 wv = W0p[kk];
            a0=fmaf(wv.x,x,a0); a1=fmaf(wv.y,x,a1); a2=fmaf(wv.z,x,a2); a3=fmaf(wv.w,x,a3);
        }
        { float* q = pb + w * 128 + lane; q[0]=a0; q[32]=a1; q[64]=a2; q[96]=a3; }
        __syncthreads();
        if (tid < 128) {
            int u = tid >> 5, b = tid & 31, uu = u0 + u;
            const float* pre = g_pre0 + ((size_t)t * B_ + b) * G4;
            float fg = pb[0*128+u*32+b] + pb[4*128+u*32+b] + pre[uu];
            float ig = pb[1*128+u*32+b] + pb[5*128+u*32+b] + pre[512  + uu];
            float og = pb[2*128+u*32+b] + pb[6*128+u*32+b] + pre[1024 + uu];
            float cc = pb[3*128+u*32+b] + pb[7*128+u*32+b] + pre[1536 + uu];
            fg=sigf(fg); ig=sigf(ig); og=sigf(og); cc=tanhf(cc);
            int idx = b * H_ + uu;
            float cn = fg * g_c0s[idx] + ig * cc;
            g_c0s[idx] = cn;
            g_h0s[p ^ 1][idx] = og * tanhf(cn);
        }
        grid_sync_();
        // ---- layer1 part B: h0new @ M1, finalize ----
        {
            const float* hp = g_h0s[p ^ 1];
            #pragma unroll 8
            for (int i = tid; i < B_ * H_; i += 256) { int b = i >> 9, k = i & 511; hT[k * 33 + b] = hp[i]; }
        }
        __syncthreads();
        #pragma unroll 8
        for (int kk = 0; kk < 256; kk++) {
            float x = xp[kk * 33]; float4 wv = M1p[kk];
            s0=fmaf(wv.x,x,s0); s1=fmaf(wv.y,x,s1); s2=fmaf(wv.z,x,s2); s3=fmaf(wv.w,x,s3);
        }
        { float* q = pb + w * 128 + lane; q[0]=s0; q[32]=s1; q[64]=s2; q[96]=s3; }
        __syncthreads();
        if (tid < 128) {
            int u = tid >> 5, b = tid & 31, uu = u0 + u;
            float fg = pb[0*128+u*32+b] + pb[4*128+u*32+b] + g_b1p[uu];
            float ig = pb[1*128+u*32+b] + pb[5*128+u*32+b] + g_b1p[512  + uu];
            float og = pb[2*128+u*32+b] + pb[6*128+u*32+b] + g_b1p[1024 + uu];
            float cc = pb[3*128+u*32+b] + pb[7*128+u*32+b] + g_b1p[1536 + uu];
            fg=sigf(fg); ig=sigf(ig); og=sigf(og); cc=tanhf(cc);
            int idx = b * H_ + uu;
            float cn = fg * g_c1s[idx] + ig * cc;
            g_c1s[idx] = cn;
            float hn = og * tanhf(cn);
            g_h1s[p ^ 1][idx] = hn;
            if (t > 0) g_Hs[((size_t)b * S_ + (t - 1)) * H_ + uu] = hn;
        }
        grid_sync_();
        p ^= 1;
    }
}

// ---------------- launch ----------------
extern "C" void kernel_launch(void* const* d_in, const int* in_sizes, int n_in,
                              void* d_out, int out_size) {
    const float* im    = (const float*)d_in[0];
    const int*   tok   = (const int*)  d_in[1];
    const float* h0    = (const float*)d_in[2];
    const float* c0    = (const float*)d_in[3];
    const float* embed = (const float*)d_in[4];
    const float* Wim   = (const float*)d_in[5];
    const float* bim   = (const float*)d_in[6];
    const float* Wh    = (const float*)d_in[7];
    const float* bw    = (const float*)d_in[8];
    const float* Uh    = (const float*)d_in[9];
    const float* bu    = (const float*)d_in[10];
    const float* Wxh   = (const float*)d_in[11];
    const float* bxh   = (const float*)d_in[12];
    const float* Wc    = (const float*)d_in[13];
    const float* bc    = (const float*)d_in[14];
    float* out = (float*)d_out;

    const size_t GEMM_SM = (size_t)(2 * 128 * ASTR + 2 * 32 * BSTR) * sizeof(float);
    cudaFuncSetAttribute(gemm_tf32, cudaFuncAttributeMaxDynamicSharedMemorySize, (int)GEMM_SM);
    cudaFuncSetAttribute(lstm_pers, cudaFuncAttributeMaxDynamicSharedMemorySize, PERS_SMEM);

    void *pXg, *pPre0, *pM1, *pB0, *pHs, *pYs;
    cudaGetSymbolAddress(&pXg,  g_Xg);
    cudaGetSymbolAddress(&pPre0,g_pre0);
    cudaGetSymbolAddress(&pM1,  g_M1);
    cudaGetSymbolAddress(&pB0,  g_b0);
    cudaGetSymbolAddress(&pHs,  g_Hs);
    cudaGetSymbolAddress(&pYs,  g_Ys);

    init_state_k<<<(B_ * H_ + 255) / 256, 256>>>(h0, c0);
    bias_prep_k<<<G4 / 256, 256>>>(bw, bu);
    b1_fold_k<<<64, 256>>>(bxh, Uh + (size_t)D_ * G4);
    gather_k<<<(S_ * B_ * (D_ / 4) + 255) / 256, 256>>>(tok, embed);

    // Xg rows 0..31 = im_feat @ W_im + b_im   [32 x 512], K=768
    gemm_tf32<<<dim3(1, 4), 256, GEMM_SM>>>(im, Wim, (float*)pXg, bim, B_, D_, F_);
    // pre0 = Xg @ Uh0 + (bw0+bu0)   [4128 x 2048]
    gemm_tf32<<<dim3(33, 16), 256, GEMM_SM>>>((const float*)pXg, Uh, (float*)pPre0,
                                              (const float*)pB0, NSTEP * B_, G4, D_);
    // M1 = Wxh0 @ Uh1               [512 x 2048]
    gemm_tf32<<<dim3(4, 16), 256, GEMM_SM>>>(Wxh, Uh + (size_t)D_ * G4, (float*)pM1,
                                             nullptr, H_, G4, H_);

    // persistent recurrence: 129 steps, 2 layers
    lstm_pers<<<128, 256, PERS_SMEM>>>(Wh, Wh + (size_t)H_ * G4);

    // Ys = Hs @ Wxh1 + bxh1         [4096 x 512]
    gemm_tf32<<<dim3(32, 4), 256, GEMM_SM>>>((const float*)pHs, Wxh + (size_t)H_ * D_,
                                             (float*)pYs, bxh + D_, MROWS, D_, H_);
    // logits = Ys @ Wc + bc         [4096 x 32000]
    gemm_tf32<<<dim3(32, 250), 256, GEMM_SM>>>((const float*)pYs, Wc, out, bc,
                                               MROWS, V_, D_);
}

// round 4
// speedup vs baseline: 2.6036x; 1.1439x over previous
#include <cuda_runtime.h>
#include <cstdint>
#include <math.h>

#define B_   32
#define S_   128
#define H_   512
#define D_   512
#define V_   32000
#define F_   768
#define G4   2048
#define NSTEP 129
#define MROWS 4096

__device__ float g_Xg  [NSTEP * B_ * D_];
__device__ float g_pre0[NSTEP * B_ * G4];
__device__ float g_M1  [D_ * G4];
__device__ float g_b0  [G4];
__device__ float g_b1p [G4];
__device__ float g_h0sT[2][B_ * H_];   // transposed: [k*32+b]
__device__ float g_c0s [B_ * H_];
__device__ float g_h1sT[2][B_ * H_];
__device__ float g_c1s [B_ * H_];
__device__ float g_Hs  [MROWS * H_];
__device__ float g_Ys  [MROWS * D_];
__device__ volatile unsigned g_phase_v;
__device__ unsigned g_count;

__device__ __forceinline__ float f2tf32(float x) {
    float y; asm("cvt.rna.tf32.f32 %0, %1;" : "=f"(y) : "f"(x)); return y;
}
__device__ __forceinline__ uint32_t ldcvt(const float* p) {
    return __float_as_uint(f2tf32(*p));
}
__device__ __forceinline__ float sigf(float x) { return 1.f / (1.f + expf(-x)); }

// ---------------- prep kernels ----------------
__global__ void init_state_k(const float* __restrict__ h0, const float* __restrict__ c0) {
    int i = blockIdx.x * blockDim.x + threadIdx.x;
    if (i < B_ * H_) {
        int b = i >> 9, k = i & 511;
        g_h0sT[0][k * 32 + b] = h0[i];
        g_h1sT[0][k * 32 + b] = h0[B_ * H_ + i];
        g_c0s[i] = c0[i];
        g_c1s[i] = c0[B_ * H_ + i];
    }
}
__global__ void bias_prep_k(const float* __restrict__ bw, const float* __restrict__ bu) {
    int j = blockIdx.x * blockDim.x + threadIdx.x;
    if (j < G4) { g_b0[j] = bw[j] + bu[j]; g_b1p[j] = bw[G4 + j] + bu[G4 + j]; }
}
__global__ void b1_fold_k(const float* __restrict__ bxh0, const float* __restrict__ Uh1) {
    __shared__ float red[256];
    int j  = blockIdx.x * 32 + (threadIdx.x & 31);
    int sl = threadIdx.x >> 5;
    float s = 0.f;
    #pragma unroll 8
    for (int d = sl * 64; d < sl * 64 + 64; d++) s += bxh0[d] * Uh1[(size_t)d * G4 + j];
    red[threadIdx.x] = s;
    __syncthreads();
    if (threadIdx.x < 32) {
        float t = red[threadIdx.x];
        #pragma unroll
        for (int k = 1; k < 8; k++) t += red[k * 32 + threadIdx.x];
        g_b1p[j] += t;
    }
}
__global__ void gather_k(const int* __restrict__ tok, const float* __restrict__ embed) {
    int i = blockIdx.x * blockDim.x + threadIdx.x;
    if (i < S_ * B_ * (D_ / 4)) {
        int d4 = i & 127, r = i >> 7, b = r & 31, s = r >> 5;
        float4 v = ((const float4*)(embed + (size_t)tok[b * S_ + s] * D_))[d4];
        ((float4*)(g_Xg + ((size_t)(1 + s) * B_ + b) * D_))[d4] = v;
    }
}

// ---------------- TF32 GEMM via cp.async, 2 CTAs/SM ----------------
#define ASTR 36
#define BSTR 136
__device__ __forceinline__ void cp16(uint32_t dst, const void* src, int srcsize) {
    asm volatile("cp.async.cg.shared.global [%0], [%1], 16, %2;"
                 :: "r"(dst), "l"(src), "r"(srcsize));
}
#define CP_COMMIT() asm volatile("cp.async.commit_group;")

__global__ void __launch_bounds__(256, 2) gemm_tf32(
    const float* __restrict__ A, const float* __restrict__ B,
    float* __restrict__ C, const float* __restrict__ bias, int M, int N, int K)
{
    extern __shared__ float sh[];
    float* As = sh;                      // 2 x [128][36] raw fp32
    float* Bs = sh + 2 * 128 * ASTR;     // 2 x [32][136]
    const int tid = threadIdx.x, lane = tid & 31, warp = tid >> 5;
    const int gid = lane >> 2, tig = lane & 3;
    const int wm = warp & 3, wn = warp >> 2;
    const int m0 = blockIdx.x * 128, n0 = blockIdx.y * 128;

    float acc[2][8][4];
    #pragma unroll
    for (int i = 0; i < 2; i++)
        #pragma unroll
        for (int j = 0; j < 8; j++) { acc[i][j][0]=0.f; acc[i][j][1]=0.f; acc[i][j][2]=0.f; acc[i][j][3]=0.f; }

    const int ar = tid >> 3, ak = (tid & 7) << 2;
    const int bk = tid >> 5, bn = (tid & 31) << 2;
    const int KT = K >> 5;

    const uint32_t sA = (uint32_t)__cvta_generic_to_shared(As);
    const uint32_t sB = (uint32_t)__cvta_generic_to_shared(Bs);

    auto ldgsts = [&](int kt) {
        int buf = kt & 1;
        #pragma unroll
        for (int p = 0; p < 4; p++) {
            int row = m0 + ar + p * 32;
            cp16(sA + (uint32_t)(buf * (128 * ASTR) + (ar + p * 32) * ASTR + ak) * 4,
                 A + (size_t)row * K + kt * 32 + ak, (row < M) ? 16 : 0);
            cp16(sB + (uint32_t)(buf * (32 * BSTR) + (bk + p * 8) * BSTR + bn) * 4,
                 B + (size_t)(kt * 32 + bk + p * 8) * N + n0 + bn, 16);
        }
        CP_COMMIT();
    };

    ldgsts(0);

    for (int kt = 0; kt < KT; kt++) {
        const int nxt = kt + 1;
        if (nxt < KT) {
            ldgsts(nxt);
            asm volatile("cp.async.wait_group %0;" :: "n"(1));
        } else {
            asm volatile("cp.async.wait_group %0;" :: "n"(0));
        }
        __syncthreads();

        const float* Ab = As + (kt & 1) * (128 * ASTR);
        const float* Bb = Bs + (kt & 1) * (32 * BSTR);
        #pragma unroll
        for (int kk = 0; kk < 32; kk += 8) {
            uint32_t af[2][4], bf[8][2];
            #pragma unroll
            for (int mi = 0; mi < 2; mi++) {
                int r = wm * 32 + mi * 16 + gid;
                af[mi][0] = ldcvt(Ab + r       * ASTR + kk + tig);
                af[mi][1] = ldcvt(Ab + (r + 8) * ASTR + kk + tig);
                af[mi][2] = ldcvt(Ab + r       * ASTR + kk + tig + 4);
                af[mi][3] = ldcvt(Ab + (r + 8) * ASTR + kk + tig + 4);
            }
            #pragma unroll
            for (int ni = 0; ni < 8; ni++) {
                int cx = wn * 64 + ni * 8 + gid;
                bf[ni][0] = ldcvt(Bb + (kk + tig)     * BSTR + cx);
                bf[ni][1] = ldcvt(Bb + (kk + tig + 4) * BSTR + cx);
            }
            #pragma unroll
            for (int mi = 0; mi < 2; mi++)
                #pragma unroll
                for (int ni = 0; ni < 8; ni++)
                    asm volatile(
                        "mma.sync.aligned.m16n8k8.row.col.f32.tf32.tf32.f32 "
                        "{%0,%1,%2,%3}, {%4,%5,%6,%7}, {%8,%9}, {%0,%1,%2,%3};"
                        : "+f"(acc[mi][ni][0]), "+f"(acc[mi][ni][1]),
                          "+f"(acc[mi][ni][2]), "+f"(acc[mi][ni][3])
                        : "r"(af[mi][0]), "r"(af[mi][1]), "r"(af[mi][2]), "r"(af[mi][3]),
                          "r"(bf[ni][0]), "r"(bf[ni][1]));
        }
        __syncthreads();
    }

    #pragma unroll
    for (int mi = 0; mi < 2; mi++) {
        int r = m0 + wm * 32 + mi * 16 + gid;
        #pragma unroll
        for (int ni = 0; ni < 8; ni++) {
            int cx = n0 + wn * 64 + ni * 8 + tig * 2;
            float b0v = bias ? bias[cx] : 0.f, b1v = bias ? bias[cx + 1] : 0.f;
            if (r < M) {
                C[(size_t)r * N + cx]     = acc[mi][ni][0] + b0v;
                C[(size_t)r * N + cx + 1] = acc[mi][ni][1] + b1v;
            }
            if (r + 8 < M) {
                C[(size_t)(r + 8) * N + cx]     = acc[mi][ni][2] + b0v;
                C[(size_t)(r + 8) * N + cx + 1] = acc[mi][ni][3] + b1v;
            }
        }
    }
}

// ---------------- persistent LSTM recurrence (FFMA2) ----------------
__device__ __forceinline__ void grid_sync_() {
    __syncthreads();
    if (threadIdx.x == 0) {
        __threadfence();
        unsigned ph = g_phase_v;
        if (atomicAdd(&g_count, 1u) == gridDim.x - 1u) {
            g_count = 0u;
            __threadfence();
            g_phase_v = ph + 1u;
        } else {
            while (g_phase_v == ph) { }
        }
        __threadfence();
    }
    __syncthreads();
}

#define SM_W0 0
#define SM_W1 8192
#define SM_M1 16384
#define SM_HT 24576
#define SM_PB (24576 + 16896)
#define PERS_SMEM ((SM_PB + 1024) * 4)

// packed f32x2 fma: acc += w * {x,x}
__device__ __forceinline__ void fma2_(unsigned long long& acc, unsigned long long w,
                                      unsigned long long xx) {
    asm("fma.rn.f32x2 %0, %1, %2, %0;" : "+l"(acc) : "l"(w), "l"(xx));
}
__device__ __forceinline__ unsigned long long packxx_(float x) {
    unsigned long long r; asm("mov.b64 %0, {%1, %1};" : "=l"(r) : "f"(x)); return r;
}
__device__ __forceinline__ void ldsv2_(uint32_t addr, unsigned long long& a,
                                       unsigned long long& b) {
    asm("ld.shared.v2.u64 {%0,%1}, [%2];" : "=l"(a), "=l"(b) : "r"(addr));
}
__device__ __forceinline__ void unpack2_(unsigned long long v, float& a, float& b) {
    asm("mov.b64 {%0,%1}, %2;" : "=f"(a), "=f"(b) : "l"(v));
}

__global__ void __launch_bounds__(256, 1) lstm_pers(const float* __restrict__ Wh0,
                                                    const float* __restrict__ Wh1) {
    extern __shared__ float sh[];
    float4* Ws0 = (float4*)(sh + SM_W0);
    float4* Ws1 = (float4*)(sh + SM_W1);
    float4* Ms1 = (float4*)(sh + SM_M1);
    float*  hT  = sh + SM_HT;     // [512][33]
    float*  pb  = sh + SM_PB;     // [8][4][32]
    const int tid = threadIdx.x, lane = tid & 31, w = tid >> 5;
    const int half = w >> 2;
    const int u0 = blockIdx.x << 2;

    for (int f4 = tid; f4 < 2048; f4 += 256) {
        int ww = f4 >> 8, kk = f4 & 255;
        int gg = ww & 3, hh = ww >> 2;
        size_t off = (size_t)(hh * 256 + kk) * G4 + gg * 512 + u0;
        Ws0[f4] = *(const float4*)(Wh0  + off);
        Ws1[f4] = *(const float4*)(Wh1  + off);
        Ms1[f4] = *(const float4*)(g_M1 + off);
    }

    const uint32_t w0a = (uint32_t)__cvta_generic_to_shared(Ws0) + (w << 12);
    const uint32_t w1a = (uint32_t)__cvta_generic_to_shared(Ws1) + (w << 12);
    const uint32_t m1a = (uint32_t)__cvta_generic_to_shared(Ms1) + (w << 12);
    const float*   xp  = hT + (half * 256) * 33 + lane;

    int p = 0;
    for (int t = 0; t < NSTEP; t++) {
        __syncthreads();
        // ---- layer1 part A: h1[p] @ Wh1 ----
        {
            const float* hp = g_h1sT[p];
            #pragma unroll 8
            for (int i = tid; i < B_ * H_; i += 256) { int k = i >> 5, b = i & 31; hT[k * 33 + b] = hp[i]; }
        }
        __syncthreads();
        unsigned long long s01 = 0ull, s23 = 0ull;
        #pragma unroll 8
        for (int kk = 0; kk < 256; kk++) {
            unsigned long long xx = packxx_(xp[kk * 33]);
            unsigned long long v0, v1;
            ldsv2_(w1a + (kk << 4), v0, v1);
            fma2_(s01, v0, xx); fma2_(s23, v1, xx);
        }
        __syncthreads();
        // ---- layer0: h0[p] @ Wh0 + pre0[t] ----
        {
            const float* hp = g_h0sT[p];
            #pragma unroll 8
            for (int i = tid; i < B_ * H_; i += 256) { int k = i >> 5, b = i & 31; hT[k * 33 + b] = hp[i]; }
        }
        __syncthreads();
        unsigned long long a01 = 0ull, a23 = 0ull;
        #pragma unroll 8
        for (int kk = 0; kk < 256; kk++) {
            unsigned long long xx = packxx_(xp[kk * 33]);
            unsigned long long v0, v1;
            ldsv2_(w0a + (kk << 4), v0, v1);
            fma2_(a01, v0, xx); fma2_(a23, v1, xx);
        }
        {
            float a0, a1, a2, a3;
            unpack2_(a01, a0, a1); unpack2_(a23, a2, a3);
            float* q = pb + w * 128 + lane;
            q[0] = a0; q[32] = a1; q[64] = a2; q[96] = a3;
        }
        __syncthreads();
        if (tid < 128) {
            int u = tid >> 5, b = tid & 31, uu = u0 + u;
            const float* pre = g_pre0 + ((size_t)t * B_ + b) * G4;
            float fg = pb[0*128+u*32+b] + pb[4*128+u*32+b] + pre[uu];
            float ig = pb[1*128+u*32+b] + pb[5*128+u*32+b] + pre[512  + uu];
            float og = pb[2*128+u*32+b] + pb[6*128+u*32+b] + pre[1024 + uu];
            float cc = pb[3*128+u*32+b] + pb[7*128+u*32+b] + pre[1536 + uu];
            fg=sigf(fg); ig=sigf(ig); og=sigf(og); cc=tanhf(cc);
            int idx = b * H_ + uu;
            float cn = fg * g_c0s[idx] + ig * cc;
            g_c0s[idx] = cn;
            g_h0sT[p ^ 1][uu * 32 + b] = og * tanhf(cn);
        }
        grid_sync_();
        // ---- layer1 part B: h0new @ M1, finalize ----
        {
            const float* hp = g_h0sT[p ^ 1];
            #pragma unroll 8
            for (int i = tid; i < B_ * H_; i += 256) { int k = i >> 5, b = i & 31; hT[k * 33 + b] = hp[i]; }
        }
        __syncthreads();
        #pragma unroll 8
        for (int kk = 0; kk < 256; kk++) {
            unsigned long long xx = packxx_(xp[kk * 33]);
            unsigned long long v0, v1;
            ldsv2_(m1a + (kk << 4), v0, v1);
            fma2_(s01, v0, xx); fma2_(s23, v1, xx);
        }
        {
            float s0, s1, s2, s3;
            unpack2_(s01, s0, s1); unpack2_(s23, s2, s3);
            float* q = pb + w * 128 + lane;
            q[0] = s0; q[32] = s1; q[64] = s2; q[96] = s3;
        }
        __syncthreads();
        if (tid < 128) {
            int u = tid >> 5, b = tid & 31, uu = u0 + u;
            float fg = pb[0*128+u*32+b] + pb[4*128+u*32+b] + g_b1p[uu];
            float ig = pb[1*128+u*32+b] + pb[5*128+u*32+b] + g_b1p[512  + uu];
            float og = pb[2*128+u*32+b] + pb[6*128+u*32+b] + g_b1p[1024 + uu];
            float cc = pb[3*128+u*32+b] + pb[7*128+u*32+b] + g_b1p[1536 + uu];
            fg=sigf(fg); ig=sigf(ig); og=sigf(og); cc=tanhf(cc);
            int idx = b * H_ + uu;
            float cn = fg * g_c1s[idx] + ig * cc;
            g_c1s[idx] = cn;
            float hn = og * tanhf(cn);
            g_h1sT[p ^ 1][uu * 32 + b] = hn;
            if (t > 0) g_Hs[((size_t)b * S_ + (t - 1)) * H_ + uu] = hn;
        }
        grid_sync_();
        p ^= 1;
    }
}

// ---------------- launch ----------------
extern "C" void kernel_launch(void* const* d_in, const int* in_sizes, int n_in,
                              void* d_out, int out_size) {
    const float* im    = (const float*)d_in[0];
    const int*   tok   = (const int*)  d_in[1];
    const float* h0    = (const float*)d_in[2];
    const float* c0    = (const float*)d_in[3];
    const float* embed = (const float*)d_in[4];
    const float* Wim   = (const float*)d_in[5];
    const float* bim   = (const float*)d_in[6];
    const float* Wh    = (const float*)d_in[7];
    const float* bw    = (const float*)d_in[8];
    const float* Uh    = (const float*)d_in[9];
    const float* bu    = (const float*)d_in[10];
    const float* Wxh   = (const float*)d_in[11];
    const float* bxh   = (const float*)d_in[12];
    const float* Wc    = (const float*)d_in[13];
    const float* bc    = (const float*)d_in[14];
    float* out = (float*)d_out;

    const size_t GEMM_SM = (size_t)(2 * 128 * ASTR + 2 * 32 * BSTR) * sizeof(float);
    cudaFuncSetAttribute(gemm_tf32, cudaFuncAttributeMaxDynamicSharedMemorySize, (int)GEMM_SM);
    cudaFuncSetAttribute(lstm_pers, cudaFuncAttributeMaxDynamicSharedMemorySize, PERS_SMEM);

    void *pXg, *pPre0, *pM1, *pB0, *pHs, *pYs;
    cudaGetSymbolAddress(&pXg,  g_Xg);
    cudaGetSymbolAddress(&pPre0,g_pre0);
    cudaGetSymbolAddress(&pM1,  g_M1);
    cudaGetSymbolAddress(&pB0,  g_b0);
    cudaGetSymbolAddress(&pHs,  g_Hs);
    cudaGetSymbolAddress(&pYs,  g_Ys);

    init_state_k<<<(B_ * H_ + 255) / 256, 256>>>(h0, c0);
    bias_prep_k<<<G4 / 256, 256>>>(bw, bu);
    b1_fold_k<<<64, 256>>>(bxh, Uh + (size_t)D_ * G4);
    gather_k<<<(S_ * B_ * (D_ / 4) + 255) / 256, 256>>>(tok, embed);

    gemm_tf32<<<dim3(1, 4), 256, GEMM_SM>>>(im, Wim, (float*)pXg, bim, B_, D_, F_);
    gemm_tf32<<<dim3(33, 16), 256, GEMM_SM>>>((const float*)pXg, Uh, (float*)pPre0,
                                              (const float*)pB0, NSTEP * B_, G4, D_);
    gemm_tf32<<<dim3(4, 16), 256, GEMM_SM>>>(Wxh, Uh + (size_t)D_ * G4, (float*)pM1,
                                             nullptr, H_, G4, H_);

    lstm_pers<<<128, 256, PERS_SMEM>>>(Wh, Wh + (size_t)H_ * G4);

    gemm_tf32<<<dim3(32, 4), 256, GEMM_SM>>>((const float*)pHs, Wxh + (size_t)H_ * D_,
                                             (float*)pYs, bxh + D_, MROWS, D_, H_);
    gemm_tf32<<<dim3(32, 250), 256, GEMM_SM>>>((const float*)pYs, Wc, out, bc,
                                               MROWS, V_, D_);
}